// round 17
// baseline (speedup 1.0000x reference)
#include <cuda_runtime.h>
#include <cuda_bf16.h>
#include <cstdint>

// SC2_KNN FINAL (converged after 16 measured rounds; best 12.768 us,
// ~1.2x over the 15.1 us naive baseline, rel_err 0.0).
//
// Pipeline: deformed = pc1 + pred_flow; voxelize into the (800,800,45)
// grid (cell 0.1 => multiply by 10.0f, matching XLA's A/const ->
// A*(1/const) rewrite where fp32(1/0.1f) == 10.0f exactly — using a
// true divide flips ~1 voxel boundary in 200k and fails tolerance);
// gather nn_cell from full_ids (3 channels), nn_idx from
// orig_index_grid, distance to pc2[nn_idx]. Outputs: dist[N] then
// idx[N] (as float) concatenated.
//
// Measured design map (all single-variable probes):
//  - index gathers: .cg (no L1 alloc on ~100 MB 0%-reuse set) +
//    createpolicy evict_last L2 hint (partial cross-replay L2 residency;
//    worth ~2 us) — ties .ca+hint, beats no-hint and .cv (which drops
//    L2 residency entirely: 15.1)
//  - scalar 4B gathers are wavefront-minimal (v2 covering loads: 14.5)
//  - pc1/flow/out demoted .cs evict-first (retaining them evicts gather
//    lines worth more: 14.8)
//  - 1 pt/thread maximizes warps (2 pt/thread halves warps for no MLP
//    gain: 15.1 warm); 256-thread blocks; fill granularity is 128B on
//    every load path (measured), so traffic is irreducible.
// Remaining time = L1tex random-wavefront floor (7 wf/point) overlapped
// with residual DRAM misses of a line set that oversubscribes L2.

#define GXD 800
#define GYD 800
#define GZD 45

__device__ __forceinline__ uint64_t evict_last_policy() {
    uint64_t pol;
    asm("createpolicy.fractional.L2::evict_last.b64 %0, 1.0;" : "=l"(pol));
    return pol;
}
// L1-bypass (.cg) gather with evict_last L2 hint
__device__ __forceinline__ int ldcg_hint_i32(const int* p, uint64_t pol) {
    int v;
    asm("ld.global.cg.L2::cache_hint.s32 %0, [%1], %2;"
        : "=r"(v) : "l"(p), "l"(pol));
    return v;
}
__device__ __forceinline__ float ldca_hint_f32(const float* p, uint64_t pol) {
    float v;
    asm("ld.global.ca.L2::cache_hint.f32 %0, [%1], %2;"
        : "=f"(v) : "l"(p), "l"(pol));
    return v;
}

__global__ __launch_bounds__(256) void SC2_KNN_kernel(
                               const float* __restrict__ pc1,
                               const float* __restrict__ flow,
                               const float* __restrict__ pc2,
                               const int*   __restrict__ full_ids,
                               const int*   __restrict__ grid,
                               float*       __restrict__ out,
                               int n) {
    int i = blockIdx.x * blockDim.x + threadIdx.x;
    if (i >= n) return;

    uint64_t pol = evict_last_policy();

    // coalesced streaming point loads (evict-first: no cache churn)
    float d0 = __fadd_rn(__ldcs(pc1 + 3 * i + 0), __ldcs(flow + 3 * i + 0));
    float d1 = __fadd_rn(__ldcs(pc1 + 3 * i + 1), __ldcs(flow + 3 * i + 1));
    float d2 = __fadd_rn(__ldcs(pc1 + 3 * i + 2), __ldcs(flow + 3 * i + 2));

    // voxelize: (d - min_range) * 10.0f, truncate, clip.
    int gx = (int)__fmul_rn(__fadd_rn(d0, 40.0f), 10.0f);
    int gy = (int)__fmul_rn(__fadd_rn(d1, 40.0f), 10.0f);
    int gz = (int)__fmul_rn(__fadd_rn(d2,  1.0f), 10.0f);
    gx = min(max(gx, 0), GXD - 1);
    gy = min(max(gy, 0), GYD - 1);
    gz = min(max(gz, 0), GZD - 1);

    // full_ids: shape (3, GX, GY, GZ), channel stride 28,800,000 (< 2^31).
    // .cg + evict_last: no L1 allocation, retained in L2 across replays.
    const int CH = GXD * GYD * GZD;
    int cell = (gx * GYD + gy) * GZD + gz;
    int c0 = ldcg_hint_i32(full_ids + cell,          pol);
    int c1 = ldcg_hint_i32(full_ids + CH + cell,     pol);
    int c2 = ldcg_hint_i32(full_ids + 2 * CH + cell, pol);

    // orig_index_grid: shape (GX, GY, GZ) — same policy.
    int nn = ldcg_hint_i32(grid + (c0 * GYD + c1) * GZD + c2, pol);

    // pc2[3*nn..3*nn+2]: .ca + evict_last — the only L1-resident array.
    float x = ldca_hint_f32(pc2 + 3 * nn + 0, pol) - d0;
    float y = ldca_hint_f32(pc2 + 3 * nn + 1, pol) - d1;
    float z = ldca_hint_f32(pc2 + 3 * nn + 2, pol) - d2;
    float dist = sqrtf(x * x + y * y + z * z);

    __stcs(out + i,     dist);
    __stcs(out + n + i, (float)nn);
}

extern "C" void kernel_launch(void* const* d_in, const int* in_sizes, int n_in,
                              void* d_out, int out_size) {
    const float* pc1      = (const float*)d_in[0];
    const float* flow     = (const float*)d_in[1];
    const float* pc2      = (const float*)d_in[2];
    const int*   full_ids = (const int*)d_in[3];
    const int*   grid     = (const int*)d_in[4];
    float*       out      = (float*)d_out;

    int n = in_sizes[0] / 3;           // pc1 has (1, N, 3) -> 3N elements
    int threads = 256;
    int blocks  = (n + threads - 1) / threads;
    SC2_KNN_kernel<<<blocks, threads>>>(pc1, flow, pc2, full_ids, grid, out, n);
}